// round 14
// baseline (speedup 1.0000x reference)
#include <cuda_runtime.h>
#include <cuda_bf16.h>
#include <cstdint>

// VQ codebook quantization via mma.sync bf16 (3-term split, fp32-exact).
//   s[n,k] = z[n]·e[k] - 0.5*||e[k]||^2 ; idx[n] = argmax_k s ; out = e[idx]
// N=65536, D=64, K=1024. Output: [N*D quantized][N indices-as-float].
//
// R14: cp.async double-buffered e staging (stage chunk c+1 during compute of
// chunk c) + MMA reorder so every ldmatrix lands under tensor work:
// per tile: 8 bl-MMAs -> prefetch bl' under 16 bh-MMAs -> prefetch bh' at
// tile end (covered by next tile's bl-MMAs). -cn baked into dh init.

#define DDIM 64
#define TKC  128
#define EPB  144          // bytes per e row in smem (conflict-free ldmatrix)
#define KMAX 1024

// dynamic smem layout (bytes)
#define CNS_OFF  0                    // 1024 floats
#define BUF_OFF  4096
#define TERM_SZ  (TKC * EPB)          // 18432
#define BUF_SZ   (2 * TERM_SZ)        // 36864 (eh, el)
#define IDX_OFF  (BUF_OFF + 2 * BUF_SZ)   // 77824
#define SMEM_TOTAL (IDX_OFF + 256 * 4)    // 78848

__device__ float g_cnorm[KMAX];
__device__ __align__(16) __nv_bfloat16 g_eh[KMAX * DDIM];
__device__ __align__(16) __nv_bfloat16 g_el[KMAX * DDIM];

__global__ void prep_kernel(const float* __restrict__ emb, int K) {
    int k = blockIdx.x * blockDim.x + threadIdx.x;
    if (k < K) {
        float s = 0.f;
#pragma unroll
        for (int d = 0; d < DDIM; d++) {
            float v = emb[(size_t)k * DDIM + d];
            s += v * v;
            __nv_bfloat16 h = __float2bfloat16(v);
            g_eh[(size_t)k * DDIM + d] = h;
            g_el[(size_t)k * DDIM + d] =
                __float2bfloat16(v - __bfloat162float(h));
        }
        g_cnorm[k] = 0.5f * s;
    }
}

__device__ __forceinline__ uint32_t smem_u32(const void* p) {
    uint32_t a;
    asm("{ .reg .u64 t; cvta.to.shared.u64 t, %1; cvt.u32.u64 %0, t; }"
        : "=r"(a) : "l"(p));
    return a;
}
__device__ __forceinline__ uint64_t gmem_u64(const void* p) {
    uint64_t a;
    asm("cvta.to.global.u64 %0, %1;" : "=l"(a) : "l"(p));
    return a;
}
__device__ __forceinline__ uint32_t pack_bf16x2(float x, float y) {
    __nv_bfloat162 h;
    h.x = __float2bfloat16(x);
    h.y = __float2bfloat16(y);
    return *reinterpret_cast<uint32_t*>(&h);
}
__device__ __forceinline__ uint32_t pack_res(float x, float y, uint32_t hp) {
    __nv_bfloat162 h = *reinterpret_cast<__nv_bfloat162*>(&hp);
    __nv_bfloat162 l;
    l.x = __float2bfloat16(x - __bfloat162float(h.x));
    l.y = __float2bfloat16(y - __bfloat162float(h.y));
    return *reinterpret_cast<uint32_t*>(&l);
}
#define MMA16816(d, a, b0, b1) \
    asm volatile( \
        "mma.sync.aligned.m16n8k16.row.col.f32.bf16.bf16.f32 " \
        "{%0,%1,%2,%3},{%4,%5,%6,%7},{%8,%9},{%0,%1,%2,%3};" \
        : "+f"((d)[0]), "+f"((d)[1]), "+f"((d)[2]), "+f"((d)[3]) \
        : "r"((a)[0]), "r"((a)[1]), "r"((a)[2]), "r"((a)[3]), "r"(b0), "r"(b1))
#define LDMX4(r0, r1, r2, r3, a) \
    asm volatile("ldmatrix.sync.aligned.m8n8.x4.shared.b16 {%0,%1,%2,%3}, [%4];" \
                 : "=r"(r0), "=r"(r1), "=r"(r2), "=r"(r3) : "r"(a))
#define CP16(sdst, gsrc) \
    asm volatile("cp.async.cg.shared.global [%0], [%1], 16;" \
                 :: "r"(sdst), "l"(gsrc) : "memory")
#define CP_COMMIT() asm volatile("cp.async.commit_group;" ::: "memory")
#define CP_WAIT0()  asm volatile("cp.async.wait_group 0;" ::: "memory")

__device__ __forceinline__ void build_afrag(const float* z, int r0, int qsub,
                                            uint32_t ah[4][4], uint32_t al[4][4]) {
    const int r1 = r0 + 8;
#pragma unroll
    for (int ks = 0; ks < 4; ks++) {
        int k0 = ks * 16 + qsub * 2;
        float2 v00 = *reinterpret_cast<const float2*>(z + (size_t)r0 * DDIM + k0);
        float2 v01 = *reinterpret_cast<const float2*>(z + (size_t)r0 * DDIM + k0 + 8);
        float2 v10 = *reinterpret_cast<const float2*>(z + (size_t)r1 * DDIM + k0);
        float2 v11 = *reinterpret_cast<const float2*>(z + (size_t)r1 * DDIM + k0 + 8);
        ah[ks][0] = pack_bf16x2(v00.x, v00.y);
        ah[ks][1] = pack_bf16x2(v10.x, v10.y);
        ah[ks][2] = pack_bf16x2(v01.x, v01.y);
        ah[ks][3] = pack_bf16x2(v11.x, v11.y);
        al[ks][0] = pack_res(v00.x, v00.y, ah[ks][0]);
        al[ks][1] = pack_res(v10.x, v10.y, ah[ks][1]);
        al[ks][2] = pack_res(v01.x, v01.y, ah[ks][2]);
        al[ks][3] = pack_res(v11.x, v11.y, ah[ks][3]);
    }
}

__global__ __launch_bounds__(256, 2)
void vq_kernel(const float* __restrict__ z, const float* __restrict__ emb,
               float* __restrict__ out, int N, int K, int write_idx) {
    extern __shared__ __align__(16) char smem[];
    float* cns = reinterpret_cast<float*>(smem + CNS_OFF);
    int* finalIdx = reinterpret_cast<int*>(smem + IDX_OFF);
    const uint32_t sb = smem_u32(smem);

    const int tid = threadIdx.x;
    const int wid = tid >> 5;
    const int lane = tid & 31;
    const int qid = lane >> 2;
    const int qsub = lane & 3;
    const int rowBase = blockIdx.x * 256;

    // ---- A fragments for two 16-row tiles (32 rows per warp) ----
    uint32_t ah0[4][4], al0[4][4], ah1[4][4], al1[4][4];
    const int r0 = rowBase + wid * 32 + qid;
    build_afrag(z, r0, qsub, ah0, al0);
    build_afrag(z, r0 + 16, qsub, ah1, al1);

    for (int i = tid; i < K; i += 256) cns[i] = g_cnorm[i];

    // staging source/dst precompute (each thread copies 4 eh + 4 el uint4)
    const int s_code = tid >> 1;             // 0..127 (2 threads per code)
    const int s_q0 = (tid & 1) * 4;          // q 0..3 or 4..7
    const uint64_t g_eh_base = gmem_u64(g_eh);
    const uint64_t g_el_base = gmem_u64(g_el);
    const uint32_t s_dst = sb + BUF_OFF + s_code * EPB + s_q0 * 16;

    // stage chunk 0 into buffer 0
    {
        uint64_t gh = g_eh_base + (size_t)s_code * 128 + s_q0 * 16;
        uint64_t gl = g_el_base + (size_t)s_code * 128 + s_q0 * 16;
#pragma unroll
        for (int q = 0; q < 4; q++) {
            CP16(s_dst + q * 16, gh + q * 16);
            CP16(s_dst + TERM_SZ + q * 16, gl + q * 16);
        }
        CP_COMMIT();
    }

    const uint32_t lm_lane = (lane & 7) * EPB + (lane >> 3) * 16;
    const float NEG = -3.402823466e38f;
    float best[4] = {NEG, NEG, NEG, NEG};
    int bidx[4] = {0, 0, 0, 0};

    const int nchunks = K / TKC;   // 8
    for (int c = 0; c < nchunks; c++) {
        CP_WAIT0();
        __syncthreads();
        // stage chunk c+1 into the other buffer (overlaps compute below)
        if (c + 1 < nchunks) {
            uint32_t dst = s_dst + ((c + 1) & 1) * BUF_SZ;
            uint64_t gh = g_eh_base + (size_t)(c + 1) * TKC * 128
                          + (size_t)s_code * 128 + s_q0 * 16;
            uint64_t gl = g_el_base + (size_t)(c + 1) * TKC * 128
                          + (size_t)s_code * 128 + s_q0 * 16;
#pragma unroll
            for (int q = 0; q < 4; q++) {
                CP16(dst + q * 16, gh + q * 16);
                CP16(dst + TERM_SZ + q * 16, gl + q * 16);
            }
            CP_COMMIT();
        }

        const uint32_t eh_b = sb + BUF_OFF + (c & 1) * BUF_SZ;
        const uint32_t el_b = eh_b + TERM_SZ;

        // preload b fragments for nt=0
        uint32_t bh[8], bl[8];
        LDMX4(bh[0], bh[1], bh[2], bh[3], eh_b + lm_lane);
        LDMX4(bh[4], bh[5], bh[6], bh[7], eh_b + lm_lane + 64);
        LDMX4(bl[0], bl[1], bl[2], bl[3], el_b + lm_lane);
        LDMX4(bl[4], bl[5], bl[6], bl[7], el_b + lm_lane + 64);

#pragma unroll
        for (int nt = 0; nt < TKC / 8; nt++) {
            int code0 = c * TKC + nt * 8 + qsub * 2;
            float2 cn = *reinterpret_cast<const float2*>(&cns[code0]);
            float dh0[4] = {-cn.x, -cn.y, -cn.x, -cn.y};
            float dh1[4] = {-cn.x, -cn.y, -cn.x, -cn.y};
            float dc0[4] = {0, 0, 0, 0};
            float dc1[4] = {0, 0, 0, 0};

            // phase 1: 8 bl-consuming MMAs (zh·el) -> bl retired early
#pragma unroll
            for (int ks = 0; ks < 4; ks++) {
                MMA16816(dc0, ah0[ks], bl[2*ks], bl[2*ks+1]);
                MMA16816(dc1, ah1[ks], bl[2*ks], bl[2*ks+1]);
            }
            // prefetch bl(nt+1) under the bh burst
            if (nt + 1 < TKC / 8) {
                uint32_t lm_n = (nt + 1) * 8 * EPB + lm_lane;
                LDMX4(bl[0], bl[1], bl[2], bl[3], el_b + lm_n);
                LDMX4(bl[4], bl[5], bl[6], bl[7], el_b + lm_n + 64);
            }
            // phase 2: 16 bh-consuming MMAs (zh·eh, zl·eh)
#pragma unroll
            for (int ks = 0; ks < 4; ks++) {
                MMA16816(dh0, ah0[ks], bh[2*ks], bh[2*ks+1]);
                MMA16816(dh1, ah1[ks], bh[2*ks], bh[2*ks+1]);
                MMA16816(dc0, al0[ks], bh[2*ks], bh[2*ks+1]);
                MMA16816(dc1, al1[ks], bh[2*ks], bh[2*ks+1]);
            }
            // prefetch bh(nt+1); lands under next tile's bl-MMAs + fold
            if (nt + 1 < TKC / 8) {
                uint32_t lm_n = (nt + 1) * 8 * EPB + lm_lane;
                LDMX4(bh[0], bh[1], bh[2], bh[3], eh_b + lm_n);
                LDMX4(bh[4], bh[5], bh[6], bh[7], eh_b + lm_n + 64);
            }

            // fold (cn already folded into dh)
            float s;
            s = dh0[0] + dc0[0];
            if (s > best[0]) { best[0] = s; bidx[0] = code0; }
            s = dh0[1] + dc0[1];
            if (s > best[0]) { best[0] = s; bidx[0] = code0 + 1; }
            s = dh0[2] + dc0[2];
            if (s > best[1]) { best[1] = s; bidx[1] = code0; }
            s = dh0[3] + dc0[3];
            if (s > best[1]) { best[1] = s; bidx[1] = code0 + 1; }
            s = dh1[0] + dc1[0];
            if (s > best[2]) { best[2] = s; bidx[2] = code0; }
            s = dh1[1] + dc1[1];
            if (s > best[2]) { best[2] = s; bidx[2] = code0 + 1; }
            s = dh1[2] + dc1[2];
            if (s > best[3]) { best[3] = s; bidx[3] = code0; }
            s = dh1[3] + dc1[3];
            if (s > best[3]) { best[3] = s; bidx[3] = code0 + 1; }
        }
    }

    // ---- quad-lane reduce, index tie-break ----
#pragma unroll
    for (int off = 1; off < 4; off <<= 1) {
#pragma unroll
        for (int r = 0; r < 4; r++) {
            float v = __shfl_xor_sync(0xFFFFFFFFu, best[r], off);
            int i = __shfl_xor_sync(0xFFFFFFFFu, bidx[r], off);
            if (v > best[r] || (v == best[r] && i < bidx[r])) {
                best[r] = v; bidx[r] = i;
            }
        }
    }
    if (qsub == 0) {
#pragma unroll
        for (int r = 0; r < 4; r++)
            finalIdx[wid * 32 + qid + r * 8] = bidx[r];
    }
    __syncthreads();

    if (write_idx)
        out[(size_t)N * DDIM + rowBase + tid] = (float)finalIdx[tid];

    // ---- gather quantized rows (emb rows L2-hot) ----
#pragma unroll
    for (int t = 0; t < 16; t++) {
        int idx = tid + t * 256;
        int row = idx >> 4;
        int c4 = idx & 15;
        float4 v = reinterpret_cast<const float4*>(
            emb + (size_t)finalIdx[row] * DDIM)[c4];
        reinterpret_cast<float4*>(out + (size_t)(rowBase + row) * DDIM)[c4] = v;
    }
}

extern "C" void kernel_launch(void* const* d_in, const int* in_sizes, int n_in,
                              void* d_out, int out_size) {
    const float* z = (const float*)d_in[0];
    const float* emb = (const float*)d_in[1];
    if (n_in >= 2 && in_sizes[1] > in_sizes[0]) {
        const float* t = z; z = emb; emb = t;
    }
    int zsize = in_sizes[0], esize = in_sizes[1];
    if (esize > zsize) { int t = zsize; zsize = esize; esize = t; }

    int N = zsize / DDIM;   // 65536
    int K = esize / DDIM;   // 1024
    float* out = (float*)d_out;
    int write_idx = (out_size >= N * DDIM + N) ? 1 : 0;

    prep_kernel<<<(K + 255) / 256, 256>>>(emb, K);

    static int attr_set = 0;
    if (!attr_set) {
        cudaFuncSetAttribute(vq_kernel,
                             cudaFuncAttributeMaxDynamicSharedMemorySize,
                             SMEM_TOTAL);
        attr_set = 1;
    }
    vq_kernel<<<N / 256, 256, SMEM_TOTAL>>>(z, emb, out, N, K, write_idx);
}